// round 1
// baseline (speedup 1.0000x reference)
#include <cuda_runtime.h>
#include <cuda_fp16.h>
#include <stdint.h>

#define T 1024
#define Hd 1024
#define Id 1024
#define NE 16
#define TOPK 4

// ---------------- scratch (no runtime allocation allowed) ----------------
__device__ __align__(16) __half g_xn[T * Hd];          // normed activations, fp16
__device__ int   g_cnt[NE];                            // tokens per expert
__device__ int   g_perm[NE * T];                       // token index per (expert, slot)
__device__ float g_gate[NE * T];                       // gate per (expert, slot)
__device__ __align__(16) __half g_s[(size_t)NE * T * Id]; // swiglu output, fp16

// ---------------- kernel 0: residual init + count reset ----------------
__global__ void k_init(const float* __restrict__ x, float* __restrict__ out) {
    int idx = blockIdx.x * 256 + threadIdx.x;   // 262144 float4 = 1M floats
    ((float4*)out)[idx] = ((const float4*)x)[idx];
    if (blockIdx.x == 0 && threadIdx.x < NE) g_cnt[threadIdx.x] = 0;
}

// ---------------- kernel 1: RMSNorm + router (one block per token) ----------------
__global__ __launch_bounds__(256) void k_norm_route(
    const float* __restrict__ x, const float* __restrict__ ns,
    const float* __restrict__ wg, const float* __restrict__ bg)
{
    int t = blockIdx.x;
    int tid = threadIdx.x;
    int lane = tid & 31, warp = tid >> 5;

    const float4 xv = ((const float4*)(x + (size_t)t * Hd))[tid];
    float ss = xv.x * xv.x + xv.y * xv.y + xv.z * xv.z + xv.w * xv.w;
    #pragma unroll
    for (int o = 16; o; o >>= 1) ss += __shfl_xor_sync(0xffffffffu, ss, o);

    __shared__ float sred[8];
    __shared__ float slog[8][16];
    __shared__ float logits[16];
    if (lane == 0) sred[warp] = ss;
    __syncthreads();
    float tot = sred[0] + sred[1] + sred[2] + sred[3] + sred[4] + sred[5] + sred[6] + sred[7];
    float rms = rsqrtf(tot * (1.0f / Hd) + 1e-5f);

    int h0 = tid * 4;
    float xn0 = xv.x * rms * ns[h0 + 0];
    float xn1 = xv.y * rms * ns[h0 + 1];
    float xn2 = xv.z * rms * ns[h0 + 2];
    float xn3 = xv.w * rms * ns[h0 + 3];

    __half2* dst = (__half2*)(g_xn + (size_t)t * Hd + h0);
    dst[0] = __floats2half2_rn(xn0, xn1);
    dst[1] = __floats2half2_rn(xn2, xn3);

    // router logits in fp32 (exact-ish top-k)
    const float* w0 = wg + (size_t)h0 * NE;
    float acc[NE];
    #pragma unroll
    for (int e = 0; e < NE; e++)
        acc[e] = xn0 * w0[e] + xn1 * w0[NE + e] + xn2 * w0[2 * NE + e] + xn3 * w0[3 * NE + e];
    #pragma unroll
    for (int e = 0; e < NE; e++)
        #pragma unroll
        for (int o = 16; o; o >>= 1) acc[e] += __shfl_xor_sync(0xffffffffu, acc[e], o);
    if (lane == 0) {
        #pragma unroll
        for (int e = 0; e < NE; e++) slog[warp][e] = acc[e];
    }
    __syncthreads();
    if (tid < NE) {
        float s = bg[tid];
        #pragma unroll
        for (int w = 0; w < 8; w++) s += slog[w][tid];
        logits[tid] = s;
    }
    __syncthreads();
    if (tid == 0) {
        float vals[TOPK]; int idx[TOPK];
        unsigned used = 0;
        for (int k = 0; k < TOPK; k++) {
            float best = -1e30f; int bi = 0;
            for (int e = 0; e < NE; e++)
                if (!((used >> e) & 1u) && logits[e] > best) { best = logits[e]; bi = e; }
            used |= 1u << bi; vals[k] = best; idx[k] = bi;
        }
        float ex[TOPK], den = 0.f;
        for (int k = 0; k < TOPK; k++) { ex[k] = __expf(vals[k] - vals[0]); den += ex[k]; }
        float inv = 1.f / den;
        for (int k = 0; k < TOPK; k++) {
            int e = idx[k];
            int pos = atomicAdd(&g_cnt[e], 1);
            g_perm[e * T + pos] = t;
            g_gate[e * T + pos] = ex[k] * inv;
        }
    }
}

// ---------------- mma helper ----------------
__device__ __forceinline__ void mma16816(float* c, const uint32_t* a, const uint32_t* b) {
    asm volatile(
        "mma.sync.aligned.m16n8k16.row.col.f32.f16.f16.f32 "
        "{%0,%1,%2,%3}, {%4,%5,%6,%7}, {%8,%9}, {%0,%1,%2,%3};\n"
        : "+f"(c[0]), "+f"(c[1]), "+f"(c[2]), "+f"(c[3])
        : "r"(a[0]), "r"(a[1]), "r"(a[2]), "r"(a[3]), "r"(b[0]), "r"(b[1]));
}

// ---------------- kernel 2: grouped GEMM1 + swiglu ----------------
// grid (nTile=16, mTile=8, expert=16), block 256 (8 warps, 2x4)
__global__ __launch_bounds__(256, 2) void k_ffn1(
    const float* __restrict__ w1, const float* __restrict__ b1)
{
    int e = blockIdx.z;
    int cnt = g_cnt[e];
    int mBase = blockIdx.y * 128;
    if (mBase >= cnt) return;
    int nBase = blockIdx.x * 128;

    __shared__ __align__(16) __half As[128][40];
    __shared__ __align__(16) __half Bs[128][34];
    __shared__ int rowTok[128];

    int tid = threadIdx.x;
    if (tid < 128) {
        int slot = mBase + tid;
        rowTok[tid] = (slot < cnt) ? g_perm[e * T + slot] : -1;
    }
    __syncthreads();

    int lane = tid & 31, warp = tid >> 5;
    int wm = warp >> 2, wn = warp & 3;
    int g = lane >> 2, tg = lane & 3;

    float acc[4][4][4];
    #pragma unroll
    for (int mf = 0; mf < 4; mf++)
        #pragma unroll
        for (int nf = 0; nf < 4; nf++)
            #pragma unroll
            for (int i = 0; i < 4; i++) acc[mf][nf][i] = 0.f;

    int arow = tid >> 3;          // 0..31
    int acol = (tid & 7) * 4;     // 0..28
    int bk0  = tid >> 7;          // 0..1
    int bn   = tid & 127;

    for (int k0 = 0; k0 < Hd; k0 += 32) {
        #pragma unroll
        for (int r = 0; r < 4; r++) {
            int row = r * 32 + arow;
            int tok = rowTok[row];
            uint2 v = make_uint2(0u, 0u);
            if (tok >= 0) v = *(const uint2*)(g_xn + (size_t)tok * Hd + k0 + acol);
            *(uint2*)&As[row][acol] = v;
        }
        #pragma unroll
        for (int r = 0; r < 16; r++) {
            int k = bk0 + r * 2;
            float w = w1[((size_t)(e * Hd + k0 + k)) * (2 * Id) + nBase + bn];
            Bs[bn][k] = __float2half(w);
        }
        __syncthreads();

        #pragma unroll
        for (int kk = 0; kk < 32; kk += 16) {
            uint32_t a[4][4], b[4][2];
            #pragma unroll
            for (int mf = 0; mf < 4; mf++) {
                int row = wm * 64 + mf * 16;
                a[mf][0] = *(const uint32_t*)&As[row + g][kk + tg * 2];
                a[mf][1] = *(const uint32_t*)&As[row + g + 8][kk + tg * 2];
                a[mf][2] = *(const uint32_t*)&As[row + g][kk + tg * 2 + 8];
                a[mf][3] = *(const uint32_t*)&As[row + g + 8][kk + tg * 2 + 8];
            }
            #pragma unroll
            for (int nf = 0; nf < 4; nf++) {
                int n = wn * 32 + nf * 8 + g;
                b[nf][0] = *(const uint32_t*)&Bs[n][kk + tg * 2];
                b[nf][1] = *(const uint32_t*)&Bs[n][kk + tg * 2 + 8];
            }
            #pragma unroll
            for (int mf = 0; mf < 4; mf++)
                #pragma unroll
                for (int nf = 0; nf < 4; nf++)
                    mma16816(acc[mf][nf], a[mf], b[nf]);
        }
        __syncthreads();
    }

    // epilogue: bias + swiglu (c0,c1)=(gate,lin) pair at row g; (c2,c3) at row g+8
    #pragma unroll
    for (int mf = 0; mf < 4; mf++) {
        #pragma unroll
        for (int nf = 0; nf < 4; nf++) {
            int ncol = nBase + wn * 32 + nf * 8 + tg * 2;   // even
            float ba = b1[e * (2 * Id) + ncol];
            float bb = b1[e * (2 * Id) + ncol + 1];
            int scol = ncol >> 1;
            #pragma unroll
            for (int h = 0; h < 2; h++) {
                int row = wm * 64 + mf * 16 + g + h * 8;
                int slot = mBase + row;
                if (slot < cnt) {
                    float av = acc[mf][nf][h * 2 + 0] + ba;
                    float bv = acc[mf][nf][h * 2 + 1] + bb;
                    av = fminf(av, 7.0f);
                    bv = fminf(fmaxf(bv, -7.0f), 7.0f);
                    float sig = __frcp_rn(1.f + __expf(-1.702f * av));
                    float s = av * sig * (bv + 1.f);
                    g_s[((size_t)(e * T + slot)) * Id + scol] = __float2half(s);
                }
            }
        }
    }
}

// ---------------- kernel 3: grouped GEMM2 + gated scatter ----------------
// grid (nTile=8, mTile=8, expert=16), block 256
__global__ __launch_bounds__(256, 2) void k_ffn2(
    const float* __restrict__ w2, const float* __restrict__ b2, float* __restrict__ out)
{
    int e = blockIdx.z;
    int cnt = g_cnt[e];
    int mBase = blockIdx.y * 128;
    if (mBase >= cnt) return;
    int nBase = blockIdx.x * 128;

    __shared__ __align__(16) __half As[128][40];
    __shared__ __align__(16) __half Bs[128][34];
    __shared__ int   rowTok[128];
    __shared__ float rowGate[128];

    int tid = threadIdx.x;
    if (tid < 128) {
        int slot = mBase + tid;
        if (slot < cnt) { rowTok[tid] = g_perm[e * T + slot]; rowGate[tid] = g_gate[e * T + slot]; }
        else            { rowTok[tid] = -1;                  rowGate[tid] = 0.f; }
    }
    __syncthreads();

    int lane = tid & 31, warp = tid >> 5;
    int wm = warp >> 2, wn = warp & 3;
    int g = lane >> 2, tg = lane & 3;

    float acc[4][4][4];
    #pragma unroll
    for (int mf = 0; mf < 4; mf++)
        #pragma unroll
        for (int nf = 0; nf < 4; nf++)
            #pragma unroll
            for (int i = 0; i < 4; i++) acc[mf][nf][i] = 0.f;

    int arow = tid >> 3;
    int acol = (tid & 7) * 4;
    int bk0  = tid >> 7;
    int bn   = tid & 127;

    for (int k0 = 0; k0 < Id; k0 += 32) {
        #pragma unroll
        for (int r = 0; r < 4; r++) {
            int row = r * 32 + arow;
            // rows >= cnt hold stale-but-finite data; masked in epilogue
            *(uint2*)&As[row][acol] =
                *(const uint2*)(g_s + ((size_t)(e * T + mBase + row)) * Id + k0 + acol);
        }
        #pragma unroll
        for (int r = 0; r < 16; r++) {
            int k = bk0 + r * 2;
            float w = w2[((size_t)(e * Id + k0 + k)) * Hd + nBase + bn];
            Bs[bn][k] = __float2half(w);
        }
        __syncthreads();

        #pragma unroll
        for (int kk = 0; kk < 32; kk += 16) {
            uint32_t a[4][4], b[4][2];
            #pragma unroll
            for (int mf = 0; mf < 4; mf++) {
                int row = wm * 64 + mf * 16;
                a[mf][0] = *(const uint32_t*)&As[row + g][kk + tg * 2];
                a[mf][1] = *(const uint32_t*)&As[row + g + 8][kk + tg * 2];
                a[mf][2] = *(const uint32_t*)&As[row + g][kk + tg * 2 + 8];
                a[mf][3] = *(const uint32_t*)&As[row + g + 8][kk + tg * 2 + 8];
            }
            #pragma unroll
            for (int nf = 0; nf < 4; nf++) {
                int n = wn * 32 + nf * 8 + g;
                b[nf][0] = *(const uint32_t*)&Bs[n][kk + tg * 2];
                b[nf][1] = *(const uint32_t*)&Bs[n][kk + tg * 2 + 8];
            }
            #pragma unroll
            for (int mf = 0; mf < 4; mf++)
                #pragma unroll
                for (int nf = 0; nf < 4; nf++)
                    mma16816(acc[mf][nf], a[mf], b[nf]);
        }
        __syncthreads();
    }

    #pragma unroll
    for (int mf = 0; mf < 4; mf++) {
        #pragma unroll
        for (int nf = 0; nf < 4; nf++) {
            int ncol = nBase + wn * 32 + nf * 8 + tg * 2;
            float b2a = b2[e * Hd + ncol];
            float b2b = b2[e * Hd + ncol + 1];
            #pragma unroll
            for (int h = 0; h < 2; h++) {
                int row = wm * 64 + mf * 16 + g + h * 8;
                int slot = mBase + row;
                if (slot < cnt) {
                    int tok = rowTok[row];
                    float gt = rowGate[row];
                    atomicAdd(&out[(size_t)tok * Hd + ncol],     gt * (acc[mf][nf][h * 2 + 0] + b2a));
                    atomicAdd(&out[(size_t)tok * Hd + ncol + 1], gt * (acc[mf][nf][h * 2 + 1] + b2b));
                }
            }
        }
    }
}

// ---------------- launch ----------------
extern "C" void kernel_launch(void* const* d_in, const int* in_sizes, int n_in,
                              void* d_out, int out_size)
{
    const float* x  = (const float*)d_in[0];
    const float* ns = (const float*)d_in[1];
    const float* wg = (const float*)d_in[2];
    const float* bg = (const float*)d_in[3];
    const float* w1 = (const float*)d_in[4];
    const float* b1 = (const float*)d_in[5];
    const float* w2 = (const float*)d_in[6];
    const float* b2 = (const float*)d_in[7];
    float* out = (float*)d_out;

    k_init<<<1024, 256>>>(x, out);
    k_norm_route<<<1024, 256>>>(x, ns, wg, bg);
    k_ffn1<<<dim3(16, 8, 16), 256>>>(w1, b1);
    k_ffn2<<<dim3(8, 8, 16), 256>>>(w2, b2, out);
}

// round 2
// speedup vs baseline: 1.5008x; 1.5008x over previous
#include <cuda_runtime.h>
#include <cuda_fp16.h>
#include <stdint.h>

#define T 1024
#define Hd 1024
#define Id 1024
#define NE 16
#define TOPK 4

// ---------------- scratch (no runtime allocation allowed) ----------------
__device__ __align__(16) __half g_xn[T * Hd];             // normed activations, fp16
__device__ int   g_cnt[NE];                               // tokens per expert
__device__ int   g_perm[NE * T];                          // token index per (expert, slot)
__device__ float g_gate[NE * T];                          // gate per (expert, slot)
__device__ __align__(16) __half g_s[(size_t)NE * T * Id]; // swiglu output, fp16

// shared memory layout (dynamic): 3-stage A (fp16) + 3-stage B (fp32) + row meta
#define AS_BYTES (3 * 128 * 40 * 2)     // 30720
#define BS_BYTES (3 * 32 * 132 * 4)     // 50688
#define SMEM_BYTES (AS_BYTES + BS_BYTES + 128 * 4 + 128 * 4)   // 82432

// ---------------- kernel 0: residual init + count reset ----------------
__global__ void k_init(const float* __restrict__ x, float* __restrict__ out) {
    int idx = blockIdx.x * 256 + threadIdx.x;
    ((float4*)out)[idx] = ((const float4*)x)[idx];
    if (blockIdx.x == 0 && threadIdx.x < NE) g_cnt[threadIdx.x] = 0;
}

// ---------------- kernel 1: RMSNorm + router ----------------
__global__ __launch_bounds__(256) void k_norm_route(
    const float* __restrict__ x, const float* __restrict__ ns,
    const float* __restrict__ wg, const float* __restrict__ bg)
{
    int t = blockIdx.x;
    int tid = threadIdx.x;
    int lane = tid & 31, warp = tid >> 5;

    const float4 xv = ((const float4*)(x + (size_t)t * Hd))[tid];
    float ss = xv.x * xv.x + xv.y * xv.y + xv.z * xv.z + xv.w * xv.w;
    #pragma unroll
    for (int o = 16; o; o >>= 1) ss += __shfl_xor_sync(0xffffffffu, ss, o);

    __shared__ float sred[8];
    __shared__ float slog[8][16];
    __shared__ float logits[16];
    if (lane == 0) sred[warp] = ss;
    __syncthreads();
    float tot = sred[0] + sred[1] + sred[2] + sred[3] + sred[4] + sred[5] + sred[6] + sred[7];
    float rms = rsqrtf(tot * (1.0f / Hd) + 1e-5f);

    int h0 = tid * 4;
    float xn0 = xv.x * rms * ns[h0 + 0];
    float xn1 = xv.y * rms * ns[h0 + 1];
    float xn2 = xv.z * rms * ns[h0 + 2];
    float xn3 = xv.w * rms * ns[h0 + 3];

    __half2* dst = (__half2*)(g_xn + (size_t)t * Hd + h0);
    dst[0] = __floats2half2_rn(xn0, xn1);
    dst[1] = __floats2half2_rn(xn2, xn3);

    const float* w0 = wg + (size_t)h0 * NE;
    float acc[NE];
    #pragma unroll
    for (int e = 0; e < NE; e++)
        acc[e] = xn0 * w0[e] + xn1 * w0[NE + e] + xn2 * w0[2 * NE + e] + xn3 * w0[3 * NE + e];
    #pragma unroll
    for (int e = 0; e < NE; e++)
        #pragma unroll
        for (int o = 16; o; o >>= 1) acc[e] += __shfl_xor_sync(0xffffffffu, acc[e], o);
    if (lane == 0) {
        #pragma unroll
        for (int e = 0; e < NE; e++) slog[warp][e] = acc[e];
    }
    __syncthreads();
    if (tid < NE) {
        float s = bg[tid];
        #pragma unroll
        for (int w = 0; w < 8; w++) s += slog[w][tid];
        logits[tid] = s;
    }
    __syncthreads();
    if (tid == 0) {
        float vals[TOPK]; int idx[TOPK];
        unsigned used = 0;
        for (int k = 0; k < TOPK; k++) {
            float best = -1e30f; int bi = 0;
            for (int e = 0; e < NE; e++)
                if (!((used >> e) & 1u) && logits[e] > best) { best = logits[e]; bi = e; }
            used |= 1u << bi; vals[k] = best; idx[k] = bi;
        }
        float ex[TOPK], den = 0.f;
        for (int k = 0; k < TOPK; k++) { ex[k] = __expf(vals[k] - vals[0]); den += ex[k]; }
        float inv = 1.f / den;
        for (int k = 0; k < TOPK; k++) {
            int e = idx[k];
            int pos = atomicAdd(&g_cnt[e], 1);
            g_perm[e * T + pos] = t;
            g_gate[e * T + pos] = ex[k] * inv;
        }
    }
}

// ---------------- helpers ----------------
__device__ __forceinline__ void mma16816(float* c, const uint32_t* a, const uint32_t* b) {
    asm volatile(
        "mma.sync.aligned.m16n8k16.row.col.f32.f16.f16.f32 "
        "{%0,%1,%2,%3}, {%4,%5,%6,%7}, {%8,%9}, {%0,%1,%2,%3};\n"
        : "+f"(c[0]), "+f"(c[1]), "+f"(c[2]), "+f"(c[3])
        : "r"(a[0]), "r"(a[1]), "r"(a[2]), "r"(a[3]), "r"(b[0]), "r"(b[1]));
}
__device__ __forceinline__ void cpa16(void* dst, const void* src, int sz) {
    uint32_t d = (uint32_t)__cvta_generic_to_shared(dst);
    asm volatile("cp.async.cg.shared.global [%0], [%1], 16, %2;\n" :: "r"(d), "l"(src), "r"(sz));
}
__device__ __forceinline__ void cpa_commit() { asm volatile("cp.async.commit_group;\n"); }
__device__ __forceinline__ void cpa_wait1()  { asm volatile("cp.async.wait_group 1;\n"); }
__device__ __forceinline__ uint32_t f2toh2(float a, float b) {
    __half2 h = __floats2half2_rn(a, b);
    return *(uint32_t*)&h;
}
__device__ __forceinline__ void ldsm4(uint32_t* r, const void* p) {
    uint32_t addr = (uint32_t)__cvta_generic_to_shared(p);
    asm volatile("ldmatrix.sync.aligned.m8n8.x4.shared.b16 {%0,%1,%2,%3}, [%4];"
        : "=r"(r[0]), "=r"(r[1]), "=r"(r[2]), "=r"(r[3]) : "r"(addr));
}

// ---------------- kernel 2: grouped GEMM1 + swiglu (cp.async 3-stage) ----------------
// grid (nTile=16, mTile=8, expert=16), block 256 (8 warps, 2x4)
__global__ __launch_bounds__(256, 2) void k_ffn1(
    const float* __restrict__ w1, const float* __restrict__ b1)
{
    extern __shared__ char sm[];
    __half (*As)[128][40] = (__half(*)[128][40])sm;
    float  (*Bs)[32][132] = (float(*)[32][132])(sm + AS_BYTES);
    int* rowTok = (int*)(sm + AS_BYTES + BS_BYTES);

    int e = blockIdx.z;
    int cnt = g_cnt[e];
    int mBase = blockIdx.y * 128;
    if (mBase >= cnt) return;
    int nBase = blockIdx.x * 128;

    int tid = threadIdx.x;
    if (tid < 128) {
        int slot = mBase + tid;
        rowTok[tid] = (slot < cnt) ? g_perm[e * T + slot] : -1;
    }
    __syncthreads();

    int lane = tid & 31, warp = tid >> 5;
    int wm = warp >> 2, wn = warp & 3;
    int g = lane >> 2, tg = lane & 3;

    float acc[4][4][4];
    #pragma unroll
    for (int mf = 0; mf < 4; mf++)
        #pragma unroll
        for (int nf = 0; nf < 4; nf++)
            #pragma unroll
            for (int i = 0; i < 4; i++) acc[mf][nf][i] = 0.f;

    auto issue = [&](int buf, int k0) {
        #pragma unroll
        for (int c = 0; c < 2; c++) {                    // A: 128x32 fp16
            int ch = tid + c * 256;
            int row = ch >> 2, col = (ch & 3) * 8;
            int tok = rowTok[row];
            const __half* src = g_xn + (size_t)(tok >= 0 ? tok : 0) * Hd + k0 + col;
            cpa16(&As[buf][row][col], src, tok >= 0 ? 16 : 0);
        }
        #pragma unroll
        for (int c = 0; c < 4; c++) {                    // B: 32x128 fp32
            int ch = tid + c * 256;
            int row = ch >> 5, col = (ch & 31) * 4;
            const float* src = w1 + (size_t)(e * Hd + k0 + row) * (2 * Id) + nBase + col;
            cpa16(&Bs[buf][row][col], src, 16);
        }
    };

    issue(0, 0);  cpa_commit();
    issue(1, 32); cpa_commit();

    const int KT = Hd / 32;
    for (int it = 0; it < KT; it++) {
        cpa_wait1();
        __syncthreads();
        int buf = it - (it / 3) * 3;
        #pragma unroll
        for (int kk = 0; kk < 32; kk += 16) {
            uint32_t a[4][4], b[4][2];
            #pragma unroll
            for (int mf = 0; mf < 4; mf++) {
                int r = wm * 64 + mf * 16 + (lane & 15);
                ldsm4(a[mf], &As[buf][r][kk + (lane >> 4) * 8]);
            }
            #pragma unroll
            for (int nf = 0; nf < 4; nf++) {
                int n = wn * 32 + nf * 8 + g;
                float f0 = Bs[buf][kk + tg * 2][n];
                float f1 = Bs[buf][kk + tg * 2 + 1][n];
                float f2 = Bs[buf][kk + tg * 2 + 8][n];
                float f3 = Bs[buf][kk + tg * 2 + 9][n];
                b[nf][0] = f2toh2(f0, f1);
                b[nf][1] = f2toh2(f2, f3);
            }
            #pragma unroll
            for (int mf = 0; mf < 4; mf++)
                #pragma unroll
                for (int nf = 0; nf < 4; nf++)
                    mma16816(acc[mf][nf], a[mf], b[nf]);
        }
        if (it + 2 < KT) issue((it + 2) - ((it + 2) / 3) * 3, (it + 2) * 32);
        cpa_commit();
    }

    // epilogue: bias + swiglu
    #pragma unroll
    for (int mf = 0; mf < 4; mf++) {
        #pragma unroll
        for (int nf = 0; nf < 4; nf++) {
            int ncol = nBase + wn * 32 + nf * 8 + tg * 2;   // even
            float ba = b1[e * (2 * Id) + ncol];
            float bb = b1[e * (2 * Id) + ncol + 1];
            int scol = ncol >> 1;
            #pragma unroll
            for (int h = 0; h < 2; h++) {
                int row = wm * 64 + mf * 16 + g + h * 8;
                int slot = mBase + row;
                if (slot < cnt) {
                    float av = acc[mf][nf][h * 2 + 0] + ba;
                    float bv = acc[mf][nf][h * 2 + 1] + bb;
                    av = fminf(av, 7.0f);
                    bv = fminf(fmaxf(bv, -7.0f), 7.0f);
                    float sig = __frcp_rn(1.f + __expf(-1.702f * av));
                    float s = av * sig * (bv + 1.f);
                    g_s[((size_t)(e * T + slot)) * Id + scol] = __float2half(s);
                }
            }
        }
    }
}

// ---------------- kernel 3: grouped GEMM2 + gated scatter (cp.async 3-stage) ----------------
// grid (nTile=8, mTile=8, expert=16), block 256
__global__ __launch_bounds__(256, 2) void k_ffn2(
    const float* __restrict__ w2, const float* __restrict__ b2, float* __restrict__ out)
{
    extern __shared__ char sm[];
    __half (*As)[128][40] = (__half(*)[128][40])sm;
    float  (*Bs)[32][132] = (float(*)[32][132])(sm + AS_BYTES);
    int*   rowTok  = (int*)(sm + AS_BYTES + BS_BYTES);
    float* rowGate = (float*)(sm + AS_BYTES + BS_BYTES + 128 * 4);

    int e = blockIdx.z;
    int cnt = g_cnt[e];
    int mBase = blockIdx.y * 128;
    if (mBase >= cnt) return;
    int nBase = blockIdx.x * 128;

    int tid = threadIdx.x;
    if (tid < 128) {
        int slot = mBase + tid;
        if (slot < cnt) { rowTok[tid] = g_perm[e * T + slot]; rowGate[tid] = g_gate[e * T + slot]; }
        else            { rowTok[tid] = -1;                   rowGate[tid] = 0.f; }
    }
    __syncthreads();

    int lane = tid & 31, warp = tid >> 5;
    int wm = warp >> 2, wn = warp & 3;
    int g = lane >> 2, tg = lane & 3;

    float acc[4][4][4];
    #pragma unroll
    for (int mf = 0; mf < 4; mf++)
        #pragma unroll
        for (int nf = 0; nf < 4; nf++)
            #pragma unroll
            for (int i = 0; i < 4; i++) acc[mf][nf][i] = 0.f;

    auto issue = [&](int buf, int k0) {
        #pragma unroll
        for (int c = 0; c < 2; c++) {                    // A: 128x32 fp16 from g_s
            int ch = tid + c * 256;
            int row = ch >> 2, col = (ch & 3) * 8;
            int valid = (mBase + row < cnt) ? 16 : 0;
            const __half* src = g_s + ((size_t)(e * T + mBase + row)) * Id + k0 + col;
            cpa16(&As[buf][row][col], src, valid);
        }
        #pragma unroll
        for (int c = 0; c < 4; c++) {                    // B: 32x128 fp32
            int ch = tid + c * 256;
            int row = ch >> 5, col = (ch & 31) * 4;
            const float* src = w2 + (size_t)(e * Id + k0 + row) * Hd + nBase + col;
            cpa16(&Bs[buf][row][col], src, 16);
        }
    };

    issue(0, 0);  cpa_commit();
    issue(1, 32); cpa_commit();

    const int KT = Id / 32;
    for (int it = 0; it < KT; it++) {
        cpa_wait1();
        __syncthreads();
        int buf = it - (it / 3) * 3;
        #pragma unroll
        for (int kk = 0; kk < 32; kk += 16) {
            uint32_t a[4][4], b[4][2];
            #pragma unroll
            for (int mf = 0; mf < 4; mf++) {
                int r = wm * 64 + mf * 16 + (lane & 15);
                ldsm4(a[mf], &As[buf][r][kk + (lane >> 4) * 8]);
            }
            #pragma unroll
            for (int nf = 0; nf < 4; nf++) {
                int n = wn * 32 + nf * 8 + g;
                float f0 = Bs[buf][kk + tg * 2][n];
                float f1 = Bs[buf][kk + tg * 2 + 1][n];
                float f2 = Bs[buf][kk + tg * 2 + 8][n];
                float f3 = Bs[buf][kk + tg * 2 + 9][n];
                b[nf][0] = f2toh2(f0, f1);
                b[nf][1] = f2toh2(f2, f3);
            }
            #pragma unroll
            for (int mf = 0; mf < 4; mf++)
                #pragma unroll
                for (int nf = 0; nf < 4; nf++)
                    mma16816(acc[mf][nf], a[mf], b[nf]);
        }
        if (it + 2 < KT) issue((it + 2) - ((it + 2) / 3) * 3, (it + 2) * 32);
        cpa_commit();
    }

    #pragma unroll
    for (int mf = 0; mf < 4; mf++) {
        #pragma unroll
        for (int nf = 0; nf < 4; nf++) {
            int ncol = nBase + wn * 32 + nf * 8 + tg * 2;
            float b2a = b2[e * Hd + ncol];
            float b2b = b2[e * Hd + ncol + 1];
            #pragma unroll
            for (int h = 0; h < 2; h++) {
                int row = wm * 64 + mf * 16 + g + h * 8;
                int slot = mBase + row;
                if (slot < cnt) {
                    int tok = rowTok[row];
                    float gt = rowGate[row];
                    atomicAdd(&out[(size_t)tok * Hd + ncol],     gt * (acc[mf][nf][h * 2 + 0] + b2a));
                    atomicAdd(&out[(size_t)tok * Hd + ncol + 1], gt * (acc[mf][nf][h * 2 + 1] + b2b));
                }
            }
        }
    }
}

// ---------------- launch ----------------
extern "C" void kernel_launch(void* const* d_in, const int* in_sizes, int n_in,
                              void* d_out, int out_size)
{
    const float* x  = (const float*)d_in[0];
    const float* ns = (const float*)d_in[1];
    const float* wg = (const float*)d_in[2];
    const float* bg = (const float*)d_in[3];
    const float* w1 = (const float*)d_in[4];
    const float* b1 = (const float*)d_in[5];
    const float* w2 = (const float*)d_in[6];
    const float* b2 = (const float*)d_in[7];
    float* out = (float*)d_out;

    cudaFuncSetAttribute(k_ffn1, cudaFuncAttributeMaxDynamicSharedMemorySize, SMEM_BYTES);
    cudaFuncSetAttribute(k_ffn2, cudaFuncAttributeMaxDynamicSharedMemorySize, SMEM_BYTES);

    k_init<<<1024, 256>>>(x, out);
    k_norm_route<<<1024, 256>>>(x, ns, wg, bg);
    k_ffn1<<<dim3(16, 8, 16), 256, SMEM_BYTES>>>(w1, b1);
    k_ffn2<<<dim3(8, 8, 16), 256, SMEM_BYTES>>>(w2, b2, out);
}

// round 4
// speedup vs baseline: 1.5620x; 1.0407x over previous
#include <cuda_runtime.h>
#include <cuda_fp16.h>
#include <stdint.h>

#define T 1024
#define Hd 1024
#define Id 1024
#define NE 16
#define TOPK 4

// ---------------- scratch (no runtime allocation allowed) ----------------
__device__ __align__(16) __half g_xn[T * Hd];             // normed activations, fp16
__device__ int   g_cnt[NE];
__device__ int   g_perm[NE * T];
__device__ float g_gate[NE * T];
__device__ __align__(16) __half g_s[(size_t)NE * T * Id]; // swiglu output, fp16

// ---------------- shared memory map ----------------
// As   : 3 stages x [128][40] half          = 30720 B
// Bs32 : 3 stages x [32][132] float         = 50688 B
// B16  : 2 bufs   x [32][136] half          = 17408 B
// meta : tok/gate                           = 1024 B
#define OFF_A    0
#define OFF_B32  30720
#define OFF_B16  (30720 + 50688)            // 81408
#define OFF_TOK  (81408 + 17408)            // 98816
#define OFF_GATE (98816 + 512)
#define DYN_SMEM (98816 + 1024)             // 99840

// ---------------- kernel 0: count reset ----------------
__global__ void k_zero() { if (threadIdx.x < NE) g_cnt[threadIdx.x] = 0; }

// ---------------- kernel 1: RMSNorm + router + residual copy ----------------
__global__ __launch_bounds__(256) void k_norm_route(
    const float* __restrict__ x, const float* __restrict__ ns,
    const float* __restrict__ wg, const float* __restrict__ bg,
    float* __restrict__ out)
{
    int t = blockIdx.x;
    int tid = threadIdx.x;
    int lane = tid & 31, warp = tid >> 5;

    const float4 xv = ((const float4*)(x + (size_t)t * Hd))[tid];
    ((float4*)(out + (size_t)t * Hd))[tid] = xv;          // residual init
    float ss = xv.x * xv.x + xv.y * xv.y + xv.z * xv.z + xv.w * xv.w;
    #pragma unroll
    for (int o = 16; o; o >>= 1) ss += __shfl_xor_sync(0xffffffffu, ss, o);

    __shared__ float sred[8];
    __shared__ float slog[8][16];
    __shared__ float logits[16];
    if (lane == 0) sred[warp] = ss;
    __syncthreads();
    float tot = sred[0] + sred[1] + sred[2] + sred[3] + sred[4] + sred[5] + sred[6] + sred[7];
    float rms = rsqrtf(tot * (1.0f / Hd) + 1e-5f);

    int h0 = tid * 4;
    float xn0 = xv.x * rms * ns[h0 + 0];
    float xn1 = xv.y * rms * ns[h0 + 1];
    float xn2 = xv.z * rms * ns[h0 + 2];
    float xn3 = xv.w * rms * ns[h0 + 3];

    __half2* dst = (__half2*)(g_xn + (size_t)t * Hd + h0);
    dst[0] = __floats2half2_rn(xn0, xn1);
    dst[1] = __floats2half2_rn(xn2, xn3);

    const float* w0 = wg + (size_t)h0 * NE;
    float acc[NE];
    #pragma unroll
    for (int e = 0; e < NE; e++)
        acc[e] = xn0 * w0[e] + xn1 * w0[NE + e] + xn2 * w0[2 * NE + e] + xn3 * w0[3 * NE + e];
    #pragma unroll
    for (int e = 0; e < NE; e++)
        #pragma unroll
        for (int o = 16; o; o >>= 1) acc[e] += __shfl_xor_sync(0xffffffffu, acc[e], o);
    if (lane == 0) {
        #pragma unroll
        for (int e = 0; e < NE; e++) slog[warp][e] = acc[e];
    }
    __syncthreads();
    if (tid < NE) {
        float s = bg[tid];
        #pragma unroll
        for (int w = 0; w < 8; w++) s += slog[w][tid];
        logits[tid] = s;
    }
    __syncthreads();
    if (tid == 0) {
        float vals[TOPK]; int idx[TOPK];
        unsigned used = 0;
        for (int k = 0; k < TOPK; k++) {
            float best = -1e30f; int bi = 0;
            for (int e = 0; e < NE; e++)
                if (!((used >> e) & 1u) && logits[e] > best) { best = logits[e]; bi = e; }
            used |= 1u << bi; vals[k] = best; idx[k] = bi;
        }
        float ex[TOPK], den = 0.f;
        for (int k = 0; k < TOPK; k++) { ex[k] = __expf(vals[k] - vals[0]); den += ex[k]; }
        float inv = 1.f / den;
        for (int k = 0; k < TOPK; k++) {
            int e = idx[k];
            int pos = atomicAdd(&g_cnt[e], 1);
            g_perm[e * T + pos] = t;
            g_gate[e * T + pos] = ex[k] * inv;
        }
    }
}

// ---------------- helpers ----------------
__device__ __forceinline__ void mma16816(float* c, const uint32_t* a, const uint32_t* b) {
    asm volatile(
        "mma.sync.aligned.m16n8k16.row.col.f32.f16.f16.f32 "
        "{%0,%1,%2,%3}, {%4,%5,%6,%7}, {%8,%9}, {%0,%1,%2,%3};\n"
        : "+f"(c[0]), "+f"(c[1]), "+f"(c[2]), "+f"(c[3])
        : "r"(a[0]), "r"(a[1]), "r"(a[2]), "r"(a[3]), "r"(b[0]), "r"(b[1]));
}
__device__ __forceinline__ void cpa16(void* dst, const void* src, int sz) {
    uint32_t d = (uint32_t)__cvta_generic_to_shared(dst);
    asm volatile("cp.async.cg.shared.global [%0], [%1], 16, %2;\n" :: "r"(d), "l"(src), "r"(sz));
}
__device__ __forceinline__ void cpa_commit() { asm volatile("cp.async.commit_group;\n"); }
__device__ __forceinline__ void cpa_wait1()  { asm volatile("cp.async.wait_group 1;\n"); }
__device__ __forceinline__ uint32_t h2pack(float a, float b) {
    __half2 h = __floats2half2_rn(a, b);
    return *(uint32_t*)&h;
}
__device__ __forceinline__ void ldsm4(uint32_t* r, const void* p) {
    uint32_t addr = (uint32_t)__cvta_generic_to_shared(p);
    asm volatile("ldmatrix.sync.aligned.m8n8.x4.shared.b16 {%0,%1,%2,%3}, [%4];"
        : "=r"(r[0]), "=r"(r[1]), "=r"(r[2]), "=r"(r[3]) : "r"(addr));
}
__device__ __forceinline__ void ldsm4t(uint32_t* r, const void* p) {
    uint32_t addr = (uint32_t)__cvta_generic_to_shared(p);
    asm volatile("ldmatrix.sync.aligned.m8n8.x4.trans.shared.b16 {%0,%1,%2,%3}, [%4];"
        : "=r"(r[0]), "=r"(r[1]), "=r"(r[2]), "=r"(r[3]) : "r"(addr));
}

// ================= FFN mainloop (shared between both GEMMs) =================
// As: [3][128][40] half, Bs32: [3][32][132] float, B16: [2][32][136] half
struct SmemView {
    __half (*As)[128][40];
    float  (*Bs32)[32][132];
    __half (*B16)[32][136];
    int* rowTok;
    float* rowGate;
};
__device__ __forceinline__ SmemView smview(char* base) {
    SmemView s;
    s.As     = (__half(*)[128][40])(base + OFF_A);
    s.Bs32   = (float(*)[32][132])(base + OFF_B32);
    s.B16    = (__half(*)[32][136])(base + OFF_B16);
    s.rowTok = (int*)(base + OFF_TOK);
    s.rowGate= (float*)(base + OFF_GATE);
    return s;
}

// ---------------- kernel 2: grouped GEMM1 + swiglu ----------------
// grid (nTile=16, mTile=8, expert=16), block 256 (8 warps 2x4)
__global__ __launch_bounds__(256, 2) void k_ffn1(
    const float* __restrict__ w1, const float* __restrict__ b1)
{
    extern __shared__ char smbase[];
    SmemView sv = smview(smbase);

    int e = blockIdx.z;
    int cnt = g_cnt[e];
    int mBase = blockIdx.y * 128;
    if (mBase >= cnt) return;
    int nBase = blockIdx.x * 128;

    int tid = threadIdx.x;
    if (tid < 128) {
        int slot = mBase + tid;
        sv.rowTok[tid] = (slot < cnt) ? g_perm[e * T + slot] : -1;
    }
    __syncthreads();

    int lane = tid & 31, warp = tid >> 5;
    int wm = warp >> 2, wn = warp & 3;

    float acc[4][4][4];
    #pragma unroll
    for (int mf = 0; mf < 4; mf++)
        #pragma unroll
        for (int nf = 0; nf < 4; nf++)
            #pragma unroll
            for (int i = 0; i < 4; i++) acc[mf][nf][i] = 0.f;

    auto issue = [&](int buf, int k0) {
        #pragma unroll
        for (int c = 0; c < 2; c++) {                    // A: 128x32 half
            int ch = tid + c * 256;
            int row = ch >> 2, col = (ch & 3) * 8;
            int tok = sv.rowTok[row];
            const __half* src = g_xn + (size_t)(tok >= 0 ? tok : 0) * Hd + k0 + col;
            cpa16(&sv.As[buf][row][col], src, tok >= 0 ? 16 : 0);
        }
        #pragma unroll
        for (int c = 0; c < 4; c++) {                    // B32: 32x128 float
            int ch = tid + c * 256;
            int row = ch >> 5, col = (ch & 31) * 4;
            const float* src = w1 + (size_t)(e * Hd + k0 + row) * (2 * Id) + nBase + col;
            cpa16(&sv.Bs32[buf][row][col], src, 16);
        }
    };

    issue(0, 0);  cpa_commit();
    issue(1, 32); cpa_commit();

    int ck = tid & 31;            // convert: k row
    int cw = tid >> 5;            // convert: n chunk of 16

    const int KT = Hd / 32;
    for (int it = 0; it < KT; it++) {
        int buf = it - (it / 3) * 3;
        int cb = it & 1;
        cpa_wait1();
        __syncthreads();
        // convert B32(stage) -> B16[cb]
        {
            const float* srcr = &sv.Bs32[buf][ck][cw * 16];
            float4 v0 = ((const float4*)srcr)[0];
            float4 v1 = ((const float4*)srcr)[1];
            float4 v2 = ((const float4*)srcr)[2];
            float4 v3 = ((const float4*)srcr)[3];
            uint4 p0 = make_uint4(h2pack(v0.x, v0.y), h2pack(v0.z, v0.w),
                                  h2pack(v1.x, v1.y), h2pack(v1.z, v1.w));
            uint4 p1 = make_uint4(h2pack(v2.x, v2.y), h2pack(v2.z, v2.w),
                                  h2pack(v3.x, v3.y), h2pack(v3.z, v3.w));
            uint4* dstr = (uint4*)&sv.B16[cb][ck][cw * 16];
            dstr[0] = p0; dstr[1] = p1;
        }
        __syncthreads();
        #pragma unroll
        for (int kk = 0; kk < 32; kk += 16) {
            uint32_t a[4][4], b[4][2];
            #pragma unroll
            for (int mf = 0; mf < 4; mf++) {
                int r = wm * 64 + mf * 16 + (lane & 15);
                ldsm4(a[mf], &sv.As[buf][r][kk + (lane >> 4) * 8]);
            }
            #pragma unroll
            for (int pair = 0; pair < 2; pair++) {
                int m = lane >> 3, r = lane & 7;
                uint32_t rr[4];
                ldsm4t(rr, &sv.B16[cb][kk + (m & 1) * 8 + r][wn * 32 + pair * 16 + (m >> 1) * 8]);
                b[pair * 2 + 0][0] = rr[0]; b[pair * 2 + 0][1] = rr[1];
                b[pair * 2 + 1][0] = rr[2]; b[pair * 2 + 1][1] = rr[3];
            }
            #pragma unroll
            for (int mf = 0; mf < 4; mf++)
                #pragma unroll
                for (int nf = 0; nf < 4; nf++)
                    mma16816(acc[mf][nf], a[mf], b[nf]);
        }
        if (it + 2 < KT) issue((it + 2) - ((it + 2) / 3) * 3, (it + 2) * 32);
        cpa_commit();
    }

    int g = lane >> 2, tg = lane & 3;
    #pragma unroll
    for (int mf = 0; mf < 4; mf++) {
        #pragma unroll
        for (int nf = 0; nf < 4; nf++) {
            int ncol = nBase + wn * 32 + nf * 8 + tg * 2;   // even
            float ba = b1[e * (2 * Id) + ncol];
            float bb = b1[e * (2 * Id) + ncol + 1];
            int scol = ncol >> 1;
            #pragma unroll
            for (int h = 0; h < 2; h++) {
                int row = wm * 64 + mf * 16 + g + h * 8;
                int slot = mBase + row;
                if (slot < cnt) {
                    float av = acc[mf][nf][h * 2 + 0] + ba;
                    float bv = acc[mf][nf][h * 2 + 1] + bb;
                    av = fminf(av, 7.0f);
                    bv = fminf(fmaxf(bv, -7.0f), 7.0f);
                    float sig = __frcp_rn(1.f + __expf(-1.702f * av));
                    float s = av * sig * (bv + 1.f);
                    g_s[((size_t)(e * T + slot)) * Id + scol] = __float2half(s);
                }
            }
        }
    }
}

// ---------------- kernel 3: grouped GEMM2 + gated scatter ----------------
// grid (nTile=8, mTile=8, expert=16), block 256
__global__ __launch_bounds__(256, 2) void k_ffn2(
    const float* __restrict__ w2, const float* __restrict__ b2, float* __restrict__ out)
{
    extern __shared__ char smbase[];
    SmemView sv = smview(smbase);

    int e = blockIdx.z;
    int cnt = g_cnt[e];
    int mBase = blockIdx.y * 128;
    if (mBase >= cnt) return;
    int nBase = blockIdx.x * 128;

    int tid = threadIdx.x;
    if (tid < 128) {
        int slot = mBase + tid;
        if (slot < cnt) { sv.rowTok[tid] = g_perm[e * T + slot]; sv.rowGate[tid] = g_gate[e * T + slot]; }
        else            { sv.rowTok[tid] = -1;                   sv.rowGate[tid] = 0.f; }
    }
    __syncthreads();

    int lane = tid & 31, warp = tid >> 5;
    int wm = warp >> 2, wn = warp & 3;

    float acc[4][4][4];
    #pragma unroll
    for (int mf = 0; mf < 4; mf++)
        #pragma unroll
        for (int nf = 0; nf < 4; nf++)
            #pragma unroll
            for (int i = 0; i < 4; i++) acc[mf][nf][i] = 0.f;

    auto issue = [&](int buf, int k0) {
        #pragma unroll
        for (int c = 0; c < 2; c++) {                    // A: g_s 128x32 half
            int ch = tid + c * 256;
            int row = ch >> 2, col = (ch & 3) * 8;
            int valid = (mBase + row < cnt) ? 16 : 0;
            const __half* src = g_s + ((size_t)(e * T + mBase + row)) * Id + k0 + col;
            cpa16(&sv.As[buf][row][col], src, valid);
        }
        #pragma unroll
        for (int c = 0; c < 4; c++) {                    // B32: 32x128 float
            int ch = tid + c * 256;
            int row = ch >> 5, col = (ch & 31) * 4;
            const float* src = w2 + (size_t)(e * Id + k0 + row) * Hd + nBase + col;
            cpa16(&sv.Bs32[buf][row][col], src, 16);
        }
    };

    issue(0, 0);  cpa_commit();
    issue(1, 32); cpa_commit();

    int ck = tid & 31;
    int cw = tid >> 5;

    const int KT = Id / 32;
    for (int it = 0; it < KT; it++) {
        int buf = it - (it / 3) * 3;
        int cb = it & 1;
        cpa_wait1();
        __syncthreads();
        {
            const float* srcr = &sv.Bs32[buf][ck][cw * 16];
            float4 v0 = ((const float4*)srcr)[0];
            float4 v1 = ((const float4*)srcr)[1];
            float4 v2 = ((const float4*)srcr)[2];
            float4 v3 = ((const float4*)srcr)[3];
            uint4 p0 = make_uint4(h2pack(v0.x, v0.y), h2pack(v0.z, v0.w),
                                  h2pack(v1.x, v1.y), h2pack(v1.z, v1.w));
            uint4 p1 = make_uint4(h2pack(v2.x, v2.y), h2pack(v2.z, v2.w),
                                  h2pack(v3.x, v3.y), h2pack(v3.z, v3.w));
            uint4* dstr = (uint4*)&sv.B16[cb][ck][cw * 16];
            dstr[0] = p0; dstr[1] = p1;
        }
        __syncthreads();
        #pragma unroll
        for (int kk = 0; kk < 32; kk += 16) {
            uint32_t a[4][4], b[4][2];
            #pragma unroll
            for (int mf = 0; mf < 4; mf++) {
                int r = wm * 64 + mf * 16 + (lane & 15);
                ldsm4(a[mf], &sv.As[buf][r][kk + (lane >> 4) * 8]);
            }
            #pragma unroll
            for (int pair = 0; pair < 2; pair++) {
                int m = lane >> 3, r = lane & 7;
                uint32_t rr[4];
                ldsm4t(rr, &sv.B16[cb][kk + (m & 1) * 8 + r][wn * 32 + pair * 16 + (m >> 1) * 8]);
                b[pair * 2 + 0][0] = rr[0]; b[pair * 2 + 0][1] = rr[1];
                b[pair * 2 + 1][0] = rr[2]; b[pair * 2 + 1][1] = rr[3];
            }
            #pragma unroll
            for (int mf = 0; mf < 4; mf++)
                #pragma unroll
                for (int nf = 0; nf < 4; nf++)
                    mma16816(acc[mf][nf], a[mf], b[nf]);
        }
        if (it + 2 < KT) issue((it + 2) - ((it + 2) / 3) * 3, (it + 2) * 32);
        cpa_commit();
    }

    int g = lane >> 2, tg = lane & 3;
    #pragma unroll
    for (int mf = 0; mf < 4; mf++) {
        #pragma unroll
        for (int nf = 0; nf < 4; nf++) {
            int ncol = nBase + wn * 32 + nf * 8 + tg * 2;
            float b2a = b2[e * Hd + ncol];
            float b2b = b2[e * Hd + ncol + 1];
            #pragma unroll
            for (int h = 0; h < 2; h++) {
                int row = wm * 64 + mf * 16 + g + h * 8;
                int slot = mBase + row;
                if (slot < cnt) {
                    int tok = sv.rowTok[row];
                    float gt = sv.rowGate[row];
                    atomicAdd(&out[(size_t)tok * Hd + ncol],     gt * (acc[mf][nf][h * 2 + 0] + b2a));
                    atomicAdd(&out[(size_t)tok * Hd + ncol + 1], gt * (acc[mf][nf][h * 2 + 1] + b2b));
                }
            }
        }
    }
}

// ---------------- launch ----------------
extern "C" void kernel_launch(void* const* d_in, const int* in_sizes, int n_in,
                              void* d_out, int out_size)
{
    const float* x  = (const float*)d_in[0];
    const float* ns = (const float*)d_in[1];
    const float* wg = (const float*)d_in[2];
    const float* bg = (const float*)d_in[3];
    const float* w1 = (const float*)d_in[4];
    const float* b1 = (const float*)d_in[5];
    const float* w2 = (const float*)d_in[6];
    const float* b2 = (const float*)d_in[7];
    float* out = (float*)d_out;

    cudaFuncSetAttribute(k_ffn1, cudaFuncAttributeMaxDynamicSharedMemorySize, DYN_SMEM);
    cudaFuncSetAttribute(k_ffn2, cudaFuncAttributeMaxDynamicSharedMemorySize, DYN_SMEM);

    k_zero<<<1, 32>>>();
    k_norm_route<<<1024, 256>>>(x, ns, wg, bg, out);
    k_ffn1<<<dim3(16, 8, 16), 256, DYN_SMEM>>>(w1, b1);
    k_ffn2<<<dim3(8, 8, 16), 256, DYN_SMEM>>>(w2, b2, out);
}

// round 5
// speedup vs baseline: 1.6084x; 1.0298x over previous
#include <cuda_runtime.h>
#include <cuda_fp16.h>
#include <stdint.h>

#define T 1024
#define Hd 1024
#define Id 1024
#define NE 16
#define TOPK 4

// ---------------- scratch (no runtime allocation allowed) ----------------
__device__ __align__(16) __half g_xn[T * Hd];             // normed activations, fp16
__device__ int   g_cnt[NE];
__device__ int   g_perm[NE * T];
__device__ float g_gate[NE * T];
__device__ __align__(16) __half g_s[(size_t)NE * T * Id]; // swiglu output, fp16

// ---------------- shared memory map ----------------
// As   : 4 stages x [128][40] half          = 40960 B
// Bs32 : 3 stages x [32][132] float         = 50688 B
// B16  : 2 bufs   x [32][136] half          = 17408 B
// meta : tok/gate                           = 1024 B
#define OFF_A    0
#define OFF_B32  40960
#define OFF_B16  (40960 + 50688)            // 91648
#define OFF_TOK  (91648 + 17408)            // 109056
#define OFF_GATE (109056 + 512)
#define DYN_SMEM (109056 + 1024)            // 110080

// ---------------- kernel 0: count reset ----------------
__global__ void k_zero() { if (threadIdx.x < NE) g_cnt[threadIdx.x] = 0; }

// ---------------- kernel 1: RMSNorm + router + residual copy ----------------
__global__ __launch_bounds__(256) void k_norm_route(
    const float* __restrict__ x, const float* __restrict__ ns,
    const float* __restrict__ wg, const float* __restrict__ bg,
    float* __restrict__ out)
{
    int t = blockIdx.x;
    int tid = threadIdx.x;
    int lane = tid & 31, warp = tid >> 5;

    const float4 xv = ((const float4*)(x + (size_t)t * Hd))[tid];
    ((float4*)(out + (size_t)t * Hd))[tid] = xv;          // residual init
    float ss = xv.x * xv.x + xv.y * xv.y + xv.z * xv.z + xv.w * xv.w;
    #pragma unroll
    for (int o = 16; o; o >>= 1) ss += __shfl_xor_sync(0xffffffffu, ss, o);

    __shared__ float sred[8];
    __shared__ float slog[8][16];
    __shared__ float logits[16];
    if (lane == 0) sred[warp] = ss;
    __syncthreads();
    float tot = sred[0] + sred[1] + sred[2] + sred[3] + sred[4] + sred[5] + sred[6] + sred[7];
    float rms = rsqrtf(tot * (1.0f / Hd) + 1e-5f);

    int h0 = tid * 4;
    float xn0 = xv.x * rms * ns[h0 + 0];
    float xn1 = xv.y * rms * ns[h0 + 1];
    float xn2 = xv.z * rms * ns[h0 + 2];
    float xn3 = xv.w * rms * ns[h0 + 3];

    __half2* dst = (__half2*)(g_xn + (size_t)t * Hd + h0);
    dst[0] = __floats2half2_rn(xn0, xn1);
    dst[1] = __floats2half2_rn(xn2, xn3);

    const float* w0 = wg + (size_t)h0 * NE;
    float acc[NE];
    #pragma unroll
    for (int e = 0; e < NE; e++)
        acc[e] = xn0 * w0[e] + xn1 * w0[NE + e] + xn2 * w0[2 * NE + e] + xn3 * w0[3 * NE + e];
    #pragma unroll
    for (int e = 0; e < NE; e++)
        #pragma unroll
        for (int o = 16; o; o >>= 1) acc[e] += __shfl_xor_sync(0xffffffffu, acc[e], o);
    if (lane == 0) {
        #pragma unroll
        for (int e = 0; e < NE; e++) slog[warp][e] = acc[e];
    }
    __syncthreads();
    if (tid < NE) {
        float s = bg[tid];
        #pragma unroll
        for (int w = 0; w < 8; w++) s += slog[w][tid];
        logits[tid] = s;
    }
    __syncthreads();
    if (tid == 0) {
        float vals[TOPK]; int idx[TOPK];
        unsigned used = 0;
        for (int k = 0; k < TOPK; k++) {
            float best = -1e30f; int bi = 0;
            for (int e = 0; e < NE; e++)
                if (!((used >> e) & 1u) && logits[e] > best) { best = logits[e]; bi = e; }
            used |= 1u << bi; vals[k] = best; idx[k] = bi;
        }
        float ex[TOPK], den = 0.f;
        for (int k = 0; k < TOPK; k++) { ex[k] = __expf(vals[k] - vals[0]); den += ex[k]; }
        float inv = 1.f / den;
        for (int k = 0; k < TOPK; k++) {
            int e = idx[k];
            int pos = atomicAdd(&g_cnt[e], 1);
            g_perm[e * T + pos] = t;
            g_gate[e * T + pos] = ex[k] * inv;
        }
    }
}

// ---------------- helpers ----------------
__device__ __forceinline__ void mma16816(float* c, const uint32_t* a, const uint32_t* b) {
    asm volatile(
        "mma.sync.aligned.m16n8k16.row.col.f32.f16.f16.f32 "
        "{%0,%1,%2,%3}, {%4,%5,%6,%7}, {%8,%9}, {%0,%1,%2,%3};\n"
        : "+f"(c[0]), "+f"(c[1]), "+f"(c[2]), "+f"(c[3])
        : "r"(a[0]), "r"(a[1]), "r"(a[2]), "r"(a[3]), "r"(b[0]), "r"(b[1]));
}
__device__ __forceinline__ void cpa16(void* dst, const void* src, int sz) {
    uint32_t d = (uint32_t)__cvta_generic_to_shared(dst);
    asm volatile("cp.async.cg.shared.global [%0], [%1], 16, %2;\n" :: "r"(d), "l"(src), "r"(sz));
}
__device__ __forceinline__ void cpa_commit() { asm volatile("cp.async.commit_group;\n"); }
__device__ __forceinline__ void cpa_wait1()  { asm volatile("cp.async.wait_group 1;\n"); }
__device__ __forceinline__ void cpa_wait2()  { asm volatile("cp.async.wait_group 2;\n"); }
__device__ __forceinline__ uint32_t h2pack(float a, float b) {
    __half2 h = __floats2half2_rn(a, b);
    return *(uint32_t*)&h;
}
__device__ __forceinline__ void ldsm4(uint32_t* r, const void* p) {
    uint32_t addr = (uint32_t)__cvta_generic_to_shared(p);
    asm volatile("ldmatrix.sync.aligned.m8n8.x4.shared.b16 {%0,%1,%2,%3}, [%4];"
        : "=r"(r[0]), "=r"(r[1]), "=r"(r[2]), "=r"(r[3]) : "r"(addr));
}
__device__ __forceinline__ void ldsm4t(uint32_t* r, const void* p) {
    uint32_t addr = (uint32_t)__cvta_generic_to_shared(p);
    asm volatile("ldmatrix.sync.aligned.m8n8.x4.trans.shared.b16 {%0,%1,%2,%3}, [%4];"
        : "=r"(r[0]), "=r"(r[1]), "=r"(r[2]), "=r"(r[3]) : "r"(addr));
}

// smem views: As[4][128][40] half, Bs32[3][32][132] float, B16[2][32][136] half
struct SmemView {
    __half (*As)[128][40];
    float  (*Bs32)[32][132];
    __half (*B16)[32][136];
    int* rowTok;
    float* rowGate;
};
__device__ __forceinline__ SmemView smview(char* base) {
    SmemView s;
    s.As     = (__half(*)[128][40])(base + OFF_A);
    s.Bs32   = (float(*)[32][132])(base + OFF_B32);
    s.B16    = (__half(*)[32][136])(base + OFF_B16);
    s.rowTok = (int*)(base + OFF_TOK);
    s.rowGate= (float*)(base + OFF_GATE);
    return s;
}

// convert stage s: Bs32[s%3] (fp32 32x128) -> B16[s&1] (fp16 32x128)
__device__ __forceinline__ void convertB(SmemView& sv, int s, int tid) {
    int ck = tid & 31, cw = tid >> 5;
    const float* srcr = &sv.Bs32[s % 3][ck][cw * 16];
    float4 v0 = ((const float4*)srcr)[0];
    float4 v1 = ((const float4*)srcr)[1];
    float4 v2 = ((const float4*)srcr)[2];
    float4 v3 = ((const float4*)srcr)[3];
    uint4 p0 = make_uint4(h2pack(v0.x, v0.y), h2pack(v0.z, v0.w),
                          h2pack(v1.x, v1.y), h2pack(v1.z, v1.w));
    uint4 p1 = make_uint4(h2pack(v2.x, v2.y), h2pack(v2.z, v2.w),
                          h2pack(v3.x, v3.y), h2pack(v3.z, v3.w));
    uint4* dstr = (uint4*)&sv.B16[s & 1][ck][cw * 16];
    dstr[0] = p0; dstr[1] = p1;
}

// ---------------- kernel 2: grouped GEMM1 + swiglu ----------------
// grid (nTile=16, mTile=8, expert=16), block 256 (8 warps 2x4)
__global__ __launch_bounds__(256, 2) void k_ffn1(
    const float* __restrict__ w1, const float* __restrict__ b1)
{
    extern __shared__ char smbase[];
    SmemView sv = smview(smbase);

    int e = blockIdx.z;
    int cnt = g_cnt[e];
    int mBase = blockIdx.y * 128;
    if (mBase >= cnt) return;
    int nBase = blockIdx.x * 128;

    int tid = threadIdx.x;
    if (tid < 128) {
        int slot = mBase + tid;
        sv.rowTok[tid] = (slot < cnt) ? g_perm[e * T + slot] : -1;
    }
    __syncthreads();

    int lane = tid & 31, warp = tid >> 5;
    int wm = warp >> 2, wn = warp & 3;

    float acc[4][4][4];
    #pragma unroll
    for (int mf = 0; mf < 4; mf++)
        #pragma unroll
        for (int nf = 0; nf < 4; nf++)
            #pragma unroll
            for (int i = 0; i < 4; i++) acc[mf][nf][i] = 0.f;

    auto issue = [&](int s) {
        int k0 = s * 32;
        #pragma unroll
        for (int c = 0; c < 2; c++) {                    // A: 128x32 half
            int ch = tid + c * 256;
            int row = ch >> 2, col = (ch & 3) * 8;
            int tok = sv.rowTok[row];
            const __half* src = g_xn + (size_t)(tok >= 0 ? tok : 0) * Hd + k0 + col;
            cpa16(&sv.As[s & 3][row][col], src, tok >= 0 ? 16 : 0);
        }
        #pragma unroll
        for (int c = 0; c < 4; c++) {                    // B32: 32x128 float
            int ch = tid + c * 256;
            int row = ch >> 5, col = (ch & 31) * 4;
            const float* src = w1 + (size_t)(e * Hd + k0 + row) * (2 * Id) + nBase + col;
            cpa16(&sv.Bs32[s % 3][row][col], src, 16);
        }
    };

    issue(0); cpa_commit();
    issue(1); cpa_commit();
    issue(2); cpa_commit();
    cpa_wait2();
    __syncthreads();
    convertB(sv, 0, tid);

    const int KT = Hd / 32;
    for (int it = 0; it < KT; it++) {
        cpa_wait1();                 // stages <= it+1 landed
        __syncthreads();             // single barrier per stage
        if (it + 1 < KT) convertB(sv, it + 1, tid);
        #pragma unroll
        for (int kk = 0; kk < 32; kk += 16) {
            uint32_t a[4][4], b[4][2];
            #pragma unroll
            for (int mf = 0; mf < 4; mf++) {
                int r = wm * 64 + mf * 16 + (lane & 15);
                ldsm4(a[mf], &sv.As[it & 3][r][kk + (lane >> 4) * 8]);
            }
            #pragma unroll
            for (int pair = 0; pair < 2; pair++) {
                int m = lane >> 3, r = lane & 7;
                uint32_t rr[4];
                ldsm4t(rr, &sv.B16[it & 1][kk + (m & 1) * 8 + r][wn * 32 + pair * 16 + (m >> 1) * 8]);
                b[pair * 2 + 0][0] = rr[0]; b[pair * 2 + 0][1] = rr[1];
                b[pair * 2 + 1][0] = rr[2]; b[pair * 2 + 1][1] = rr[3];
            }
            #pragma unroll
            for (int mf = 0; mf < 4; mf++)
                #pragma unroll
                for (int nf = 0; nf < 4; nf++)
                    mma16816(acc[mf][nf], a[mf], b[nf]);
        }
        if (it + 3 < KT) issue(it + 3);
        cpa_commit();
    }

    int g = lane >> 2, tg = lane & 3;
    #pragma unroll
    for (int mf = 0; mf < 4; mf++) {
        #pragma unroll
        for (int nf = 0; nf < 4; nf++) {
            int ncol = nBase + wn * 32 + nf * 8 + tg * 2;   // even
            float ba = b1[e * (2 * Id) + ncol];
            float bb = b1[e * (2 * Id) + ncol + 1];
            int scol = ncol >> 1;
            #pragma unroll
            for (int h = 0; h < 2; h++) {
                int row = wm * 64 + mf * 16 + g + h * 8;
                int slot = mBase + row;
                if (slot < cnt) {
                    float av = acc[mf][nf][h * 2 + 0] + ba;
                    float bv = acc[mf][nf][h * 2 + 1] + bb;
                    av = fminf(av, 7.0f);
                    bv = fminf(fmaxf(bv, -7.0f), 7.0f);
                    float sig = __frcp_rn(1.f + __expf(-1.702f * av));
                    float s = av * sig * (bv + 1.f);
                    g_s[((size_t)(e * T + slot)) * Id + scol] = __float2half(s);
                }
            }
        }
    }
}

// ---------------- kernel 3: grouped GEMM2 + gated scatter ----------------
// grid (nTile=8, mTile=8, expert=16), block 256
__global__ __launch_bounds__(256, 2) void k_ffn2(
    const float* __restrict__ w2, const float* __restrict__ b2, float* __restrict__ out)
{
    extern __shared__ char smbase[];
    SmemView sv = smview(smbase);

    int e = blockIdx.z;
    int cnt = g_cnt[e];
    int mBase = blockIdx.y * 128;
    if (mBase >= cnt) return;
    int nBase = blockIdx.x * 128;

    int tid = threadIdx.x;
    if (tid < 128) {
        int slot = mBase + tid;
        if (slot < cnt) { sv.rowTok[tid] = g_perm[e * T + slot]; sv.rowGate[tid] = g_gate[e * T + slot]; }
        else            { sv.rowTok[tid] = -1;                   sv.rowGate[tid] = 0.f; }
    }
    __syncthreads();

    int lane = tid & 31, warp = tid >> 5;
    int wm = warp >> 2, wn = warp & 3;

    float acc[4][4][4];
    #pragma unroll
    for (int mf = 0; mf < 4; mf++)
        #pragma unroll
        for (int nf = 0; nf < 4; nf++)
            #pragma unroll
            for (int i = 0; i < 4; i++) acc[mf][nf][i] = 0.f;

    auto issue = [&](int s) {
        int k0 = s * 32;
        #pragma unroll
        for (int c = 0; c < 2; c++) {                    // A: g_s 128x32 half
            int ch = tid + c * 256;
            int row = ch >> 2, col = (ch & 3) * 8;
            int valid = (mBase + row < cnt) ? 16 : 0;
            const __half* src = g_s + ((size_t)(e * T + mBase + row)) * Id + k0 + col;
            cpa16(&sv.As[s & 3][row][col], src, valid);
        }
        #pragma unroll
        for (int c = 0; c < 4; c++) {                    // B32: 32x128 float
            int ch = tid + c * 256;
            int row = ch >> 5, col = (ch & 31) * 4;
            const float* src = w2 + (size_t)(e * Id + k0 + row) * Hd + nBase + col;
            cpa16(&sv.Bs32[s % 3][row][col], src, 16);
        }
    };

    issue(0); cpa_commit();
    issue(1); cpa_commit();
    issue(2); cpa_commit();
    cpa_wait2();
    __syncthreads();
    convertB(sv, 0, tid);

    const int KT = Id / 32;
    for (int it = 0; it < KT; it++) {
        cpa_wait1();
        __syncthreads();
        if (it + 1 < KT) convertB(sv, it + 1, tid);
        #pragma unroll
        for (int kk = 0; kk < 32; kk += 16) {
            uint32_t a[4][4], b[4][2];
            #pragma unroll
            for (int mf = 0; mf < 4; mf++) {
                int r = wm * 64 + mf * 16 + (lane & 15);
                ldsm4(a[mf], &sv.As[it & 3][r][kk + (lane >> 4) * 8]);
            }
            #pragma unroll
            for (int pair = 0; pair < 2; pair++) {
                int m = lane >> 3, r = lane & 7;
                uint32_t rr[4];
                ldsm4t(rr, &sv.B16[it & 1][kk + (m & 1) * 8 + r][wn * 32 + pair * 16 + (m >> 1) * 8]);
                b[pair * 2 + 0][0] = rr[0]; b[pair * 2 + 0][1] = rr[1];
                b[pair * 2 + 1][0] = rr[2]; b[pair * 2 + 1][1] = rr[3];
            }
            #pragma unroll
            for (int mf = 0; mf < 4; mf++)
                #pragma unroll
                for (int nf = 0; nf < 4; nf++)
                    mma16816(acc[mf][nf], a[mf], b[nf]);
        }
        if (it + 3 < KT) issue(it + 3);
        cpa_commit();
    }

    int g = lane >> 2, tg = lane & 3;
    #pragma unroll
    for (int mf = 0; mf < 4; mf++) {
        #pragma unroll
        for (int nf = 0; nf < 4; nf++) {
            int ncol = nBase + wn * 32 + nf * 8 + tg * 2;
            float b2a = b2[e * Hd + ncol];
            float b2b = b2[e * Hd + ncol + 1];
            #pragma unroll
            for (int h = 0; h < 2; h++) {
                int row = wm * 64 + mf * 16 + g + h * 8;
                int slot = mBase + row;
                if (slot < cnt) {
                    int tok = sv.rowTok[row];
                    float gt = sv.rowGate[row];
                    atomicAdd(&out[(size_t)tok * Hd + ncol],     gt * (acc[mf][nf][h * 2 + 0] + b2a));
                    atomicAdd(&out[(size_t)tok * Hd + ncol + 1], gt * (acc[mf][nf][h * 2 + 1] + b2b));
                }
            }
        }
    }
}

// ---------------- launch ----------------
extern "C" void kernel_launch(void* const* d_in, const int* in_sizes, int n_in,
                              void* d_out, int out_size)
{
    const float* x  = (const float*)d_in[0];
    const float* ns = (const float*)d_in[1];
    const float* wg = (const float*)d_in[2];
    const float* bg = (const float*)d_in[3];
    const float* w1 = (const float*)d_in[4];
    const float* b1 = (const float*)d_in[5];
    const float* w2 = (const float*)d_in[6];
    const float* b2 = (const float*)d_in[7];
    float* out = (float*)d_out;

    cudaFuncSetAttribute(k_ffn1, cudaFuncAttributeMaxDynamicSharedMemorySize, DYN_SMEM);
    cudaFuncSetAttribute(k_ffn2, cudaFuncAttributeMaxDynamicSharedMemorySize, DYN_SMEM);

    k_zero<<<1, 32>>>();
    k_norm_route<<<1024, 256>>>(x, ns, wg, bg, out);
    k_ffn1<<<dim3(16, 8, 16), 256, DYN_SMEM>>>(w1, b1);
    k_ffn2<<<dim3(8, 8, 16), 256, DYN_SMEM>>>(w2, b2, out);
}